// round 8
// baseline (speedup 1.0000x reference)
#include <cuda_runtime.h>
#include <math.h>

#define N_NODES 50000
#define F_IN 128
#define HID 256
#define NCLS 40
#define N_EDGES 600000
#define BN_EPS 1e-5f

// Scratch (static device globals -- no runtime allocation allowed)
__device__ float g_h0[N_NODES * F_IN];    // BN0(x)
__device__ float g_agg1[N_NODES * F_IN];  // h0 + scatter
__device__ float g_h1[N_NODES * HID];     // relu(BN1(agg1 @ W1 + b1))
__device__ float g_z[N_NODES * NCLS];     // h1 @ W2 (pre-aggregation logits)

__device__ __forceinline__ int clamp_idx(int i) {
    i = i < 0 ? 0 : i;
    return i >= N_NODES ? N_NODES - 1 : i;
}

__device__ __forceinline__ void red_add_v4(float* p, float4 v) {
    asm volatile("red.global.add.v4.f32 [%0], {%1, %2, %3, %4};"
                 :: "l"(p), "f"(v.x), "f"(v.y), "f"(v.z), "f"(v.w)
                 : "memory");
}

// ---------------------------------------------------------------------------
// K1: BN0 over input features; writes g_h0 and initializes g_agg1 (self term)
// ---------------------------------------------------------------------------
__global__ void bn0_kernel(const float4* __restrict__ x,
                           const float* __restrict__ g, const float* __restrict__ b,
                           const float* __restrict__ m, const float* __restrict__ v) {
    int idx = blockIdx.x * blockDim.x + threadIdx.x;
    const int total = N_NODES * (F_IN / 4);
    if (idx >= total) return;
    int c = (idx & (F_IN / 4 - 1)) * 4;
    float4 xv = x[idx];
    float4 o;
    o.x = (xv.x - __ldg(m + c + 0)) * (__ldg(g + c + 0) * rsqrtf(__ldg(v + c + 0) + BN_EPS)) + __ldg(b + c + 0);
    o.y = (xv.y - __ldg(m + c + 1)) * (__ldg(g + c + 1) * rsqrtf(__ldg(v + c + 1) + BN_EPS)) + __ldg(b + c + 1);
    o.z = (xv.z - __ldg(m + c + 2)) * (__ldg(g + c + 2) * rsqrtf(__ldg(v + c + 2) + BN_EPS)) + __ldg(b + c + 2);
    o.w = (xv.w - __ldg(m + c + 3)) * (__ldg(g + c + 3) * rsqrtf(__ldg(v + c + 3) + BN_EPS)) + __ldg(b + c + 3);
    ((float4*)g_h0)[idx] = o;
    ((float4*)g_agg1)[idx] = o;
}

// ---------------------------------------------------------------------------
// K2: edge scatter-add, F=128. One warp per edge; lane does one v4 reduction.
// ---------------------------------------------------------------------------
__global__ void scatter128_kernel(const int* __restrict__ src,
                                  const int* __restrict__ dst) {
    int t = blockIdx.x * blockDim.x + threadIdx.x;
    int e = t >> 5;
    if (e >= N_EDGES) return;
    int lane = t & 31;
    int s = clamp_idx(__ldg(src + e));
    int d = clamp_idx(__ldg(dst + e));
    float4 hv = ((const float4*)(g_h0 + (size_t)s * F_IN))[lane];
    float* dp = g_agg1 + (size_t)d * F_IN + lane * 4;
    red_add_v4(dp, hv);
}

// ---------------------------------------------------------------------------
// K3: GEMM1 [50000,128]x[128,256] + bias + BN1 + ReLU -> g_h1.
//     BM=128, BN=128, BK=16, 256 threads, 8x8 per thread (quadrant split).
//     A stored transposed in smem for vectorized fragment loads.
// ---------------------------------------------------------------------------
__global__ void __launch_bounds__(256, 2)
gemm1_kernel(const float* __restrict__ W1, const float* __restrict__ b1,
             const float* __restrict__ bg, const float* __restrict__ bb,
             const float* __restrict__ bm, const float* __restrict__ bv) {
    __shared__ __align__(16) float sA[16][132];   // [k][m]
    __shared__ __align__(16) float sB[16][132];   // [k][n]
    const float* A = g_agg1;
    int tid = threadIdx.x;
    int block_m = blockIdx.x * 128;
    int block_n = blockIdx.y * 128;
    int tx = tid & 15, ty = tid >> 4;

    float acc[8][8];
#pragma unroll
    for (int i = 0; i < 8; i++)
#pragma unroll
        for (int j = 0; j < 8; j++) acc[i][j] = 0.f;

    for (int kk = 0; kk < F_IN; kk += 16) {
        // A tile: rows block_m..+127, k kk..kk+15 -> transposed store.
        // 128x16 = 512 float4; 2 per thread.
#pragma unroll
        for (int i = 0; i < 2; i++) {
            int f4 = tid + i * 256;          // 0..511
            int row = f4 >> 2;               // 0..127
            int c4 = f4 & 3;                 // k-chunk 0..3
            int gr = block_m + row;
            float4 val = make_float4(0.f, 0.f, 0.f, 0.f);
            if (gr < N_NODES)
                val = ((const float4*)(A + (size_t)gr * F_IN + kk))[c4];
            sA[c4 * 4 + 0][row] = val.x;
            sA[c4 * 4 + 1][row] = val.y;
            sA[c4 * 4 + 2][row] = val.z;
            sA[c4 * 4 + 3][row] = val.w;
        }
        // B tile: W1 rows kk..kk+15, cols block_n..+127. 512 float4; 2/thread.
#pragma unroll
        for (int i = 0; i < 2; i++) {
            int f4 = tid + i * 256;
            int k = f4 >> 5;                 // 0..15
            int c4 = f4 & 31;                // 0..31
            float4 val = ((const float4*)(W1 + (size_t)(kk + k) * HID + block_n))[c4];
            *(float4*)&sB[k][c4 * 4] = val;
        }
        __syncthreads();

#pragma unroll
        for (int k = 0; k < 16; k++) {
            float4 a0 = *(const float4*)&sA[k][tx * 4];        // wait no -- rows by ty
            float4 a1 = *(const float4*)&sA[k][64 + tx * 4];
            float4 b0 = *(const float4*)&sB[k][ty * 4];
            float4 b1 = *(const float4*)&sB[k][64 + ty * 4];
            // NOTE: mapping swapped intentionally: tx -> M fragments, ty -> N
            float a[8] = {a0.x, a0.y, a0.z, a0.w, a1.x, a1.y, a1.z, a1.w};
            float bb2[8] = {b0.x, b0.y, b0.z, b0.w, b1.x, b1.y, b1.z, b1.w};
#pragma unroll
            for (int i = 0; i < 8; i++)
#pragma unroll
                for (int j = 0; j < 8; j++) acc[i][j] += a[i] * bb2[j];
        }
        __syncthreads();
    }

    // Epilogue: rows = block_m + {tx*4+i, 64+tx*4+i}, cols = block_n + {ty*4+j, 64+ty*4+j}
#pragma unroll
    for (int jh = 0; jh < 2; jh++) {
#pragma unroll
        for (int j = 0; j < 4; j++) {
            int c = block_n + jh * 64 + ty * 4 + j;
            float s = __ldg(bg + c) * rsqrtf(__ldg(bv + c) + BN_EPS);
            float mu = __ldg(bm + c);
            float be = __ldg(bb + c);
            float bias = __ldg(b1 + c);
#pragma unroll
            for (int ih = 0; ih < 2; ih++) {
#pragma unroll
                for (int i = 0; i < 4; i++) {
                    int gr = block_m + ih * 64 + tx * 4 + i;
                    if (gr < N_NODES) {
                        float val = acc[ih * 4 + i][jh * 4 + j] + bias;
                        val = (val - mu) * s + be;
                        val = fmaxf(val, 0.f);
                        g_h1[(size_t)gr * HID + c] = val;
                    }
                }
            }
        }
    }
}

// ---------------------------------------------------------------------------
// K4: GEMM2 [50000,256]x[256,40] tiled. BM=256, BN=40 (full), BK=32.
//     256 threads, each computes 8 rows x 5 cols. Writes z to g_z and
//     z + b2 (self term) to out.
// ---------------------------------------------------------------------------
__global__ void __launch_bounds__(256, 2)
gemm2_kernel(const float* __restrict__ W2, const float* __restrict__ b2,
             float* __restrict__ out) {
    __shared__ float sA[256][33];        // [row][k], odd stride -> conflict-free
    __shared__ float sB[32][41];         // [k][col]
    int tid = threadIdx.x;
    int tx = tid & 7;                    // 0..7  -> 5 cols each
    int ty = tid >> 3;                   // 0..31 -> 8 rows each
    int block_m = blockIdx.x * 256;

    float acc[8][5];
#pragma unroll
    for (int i = 0; i < 8; i++)
#pragma unroll
        for (int j = 0; j < 5; j++) acc[i][j] = 0.f;

    for (int kk = 0; kk < HID; kk += 32) {
        // A tile: 256 rows x 32 k = 2048 float4; 8 per thread
#pragma unroll
        for (int i = 0; i < 8; i++) {
            int f4 = tid + i * 256;      // 0..2047
            int row = f4 >> 3;           // 0..255
            int c4 = f4 & 7;             // 0..7
            int gr = block_m + row;
            float4 v = make_float4(0.f, 0.f, 0.f, 0.f);
            if (gr < N_NODES)
                v = ((const float4*)(g_h1 + (size_t)gr * HID + kk))[c4];
            sA[row][c4 * 4 + 0] = v.x;
            sA[row][c4 * 4 + 1] = v.y;
            sA[row][c4 * 4 + 2] = v.z;
            sA[row][c4 * 4 + 3] = v.w;
        }
        // B tile: W2 rows kk..kk+31, all 40 cols = 1280 floats; 5 per thread
#pragma unroll
        for (int i = 0; i < 5; i++) {
            int idx = tid + i * 256;     // 0..1279
            int k = idx / NCLS;
            int c = idx - k * NCLS;
            sB[k][c] = W2[(size_t)(kk + k) * NCLS + c];
        }
        __syncthreads();

#pragma unroll
        for (int k = 0; k < 32; k++) {
            float a[8], bv[5];
#pragma unroll
            for (int i = 0; i < 8; i++) a[i] = sA[ty * 8 + i][k];
#pragma unroll
            for (int j = 0; j < 5; j++) bv[j] = sB[k][tx * 5 + j];
#pragma unroll
            for (int i = 0; i < 8; i++)
#pragma unroll
                for (int j = 0; j < 5; j++) acc[i][j] += a[i] * bv[j];
        }
        __syncthreads();
    }

    // Epilogue: z -> g_z; z + b2 -> out
    float bias[5];
#pragma unroll
    for (int j = 0; j < 5; j++) bias[j] = __ldg(b2 + tx * 5 + j);
#pragma unroll
    for (int i = 0; i < 8; i++) {
        int gr = block_m + ty * 8 + i;
        if (gr < N_NODES) {
            float* zp = g_z + (size_t)gr * NCLS + tx * 5;
            float* op = out + (size_t)gr * NCLS + tx * 5;
#pragma unroll
            for (int j = 0; j < 5; j++) {
                zp[j] = acc[i][j];
                op[j] = acc[i][j] + bias[j];
            }
        }
    }
}

// ---------------------------------------------------------------------------
// K5: edge scatter-add in logit space (40 floats/edge = 10 float4 chunks).
//     out[dst] += z[src]. Thread = (edge, chunk).
// ---------------------------------------------------------------------------
__global__ void scatter40_kernel(const int* __restrict__ src,
                                 const int* __restrict__ dst,
                                 float* __restrict__ out) {
    int t = blockIdx.x * blockDim.x + threadIdx.x;
    int e = t / (NCLS / 4);
    if (e >= N_EDGES) return;
    int chunk = t - e * (NCLS / 4);
    int s = clamp_idx(__ldg(src + e));
    int d = clamp_idx(__ldg(dst + e));
    float4 v = *(const float4*)(g_z + (size_t)s * NCLS + chunk * 4);
    float* p = out + (size_t)d * NCLS + chunk * 4;
    red_add_v4(p, v);
}

// ---------------------------------------------------------------------------
extern "C" void kernel_launch(void* const* d_in, const int* in_sizes, int n_in,
                              void* d_out, int out_size) {
    const float* x = (const float*)d_in[0];
    const int* ei = (const int*)d_in[1];   // int32 (jax x64-disabled)
    const float* bn0g = (const float*)d_in[2];
    const float* bn0b = (const float*)d_in[3];
    const float* bn0m = (const float*)d_in[4];
    const float* bn0v = (const float*)d_in[5];
    const float* W1 = (const float*)d_in[6];
    const float* b1 = (const float*)d_in[7];
    const float* bn1g = (const float*)d_in[8];
    const float* bn1b = (const float*)d_in[9];
    const float* bn1m = (const float*)d_in[10];
    const float* bn1v = (const float*)d_in[11];
    const float* W2 = (const float*)d_in[12];
    const float* b2 = (const float*)d_in[13];
    float* out = (float*)d_out;

    const int* src = ei;
    const int* dst = ei + N_EDGES;

    // K1: BN0 -> g_h0, g_agg1
    {
        int total = N_NODES * (F_IN / 4);
        bn0_kernel<<<(total + 255) / 256, 256>>>((const float4*)x, bn0g, bn0b, bn0m, bn0v);
    }
    // K2: 128-dim scatter-add into g_agg1 (v4 reductions)
    {
        long long threads = (long long)N_EDGES * 32;
        scatter128_kernel<<<(int)((threads + 255) / 256), 256>>>(src, dst);
    }
    // K3: GEMM1 + BN1 + ReLU -> g_h1
    {
        dim3 grid((N_NODES + 127) / 128, HID / 128);
        gemm1_kernel<<<grid, 256>>>(W1, b1, bn1g, bn1b, bn1m, bn1v);
    }
    // K4: GEMM2 (tiled) -> g_z, out = z + b2
    {
        gemm2_kernel<<<(N_NODES + 255) / 256, 256>>>(W2, b2, out);
    }
    // K5: 40-dim scatter-add into out (associativity: (h+Ah)W = hW + A(hW))
    {
        long long threads = (long long)N_EDGES * (NCLS / 4);
        scatter40_kernel<<<(int)((threads + 255) / 256), 256>>>(src, dst, out);
    }
}

// round 9
// speedup vs baseline: 1.0328x; 1.0328x over previous
#include <cuda_runtime.h>
#include <math.h>

#define N_NODES 50000
#define F_IN 128
#define HID 256
#define NCLS 40
#define N_EDGES 600000
#define BN_EPS 1e-5f

// Scratch (static device globals -- no runtime allocation allowed)
__device__ float g_h0[N_NODES * F_IN];    // BN0(x)
__device__ float g_agg1[N_NODES * F_IN];  // h0 + scatter
__device__ float g_h1[N_NODES * HID];     // relu(BN1(agg1 @ W1 + b1))
__device__ float g_z[N_NODES * NCLS];     // h1 @ W2 (pre-aggregation logits)

__device__ __forceinline__ int clamp_idx(int i) {
    i = i < 0 ? 0 : i;
    return i >= N_NODES ? N_NODES - 1 : i;
}

__device__ __forceinline__ void red_add_v4(float* p, float4 v) {
    asm volatile("red.global.add.v4.f32 [%0], {%1, %2, %3, %4};"
                 :: "l"(p), "f"(v.x), "f"(v.y), "f"(v.z), "f"(v.w)
                 : "memory");
}

// ---------------------------------------------------------------------------
// K1: BN0 over input features; writes g_h0 and initializes g_agg1 (self term)
// ---------------------------------------------------------------------------
__global__ void bn0_kernel(const float4* __restrict__ x,
                           const float* __restrict__ g, const float* __restrict__ b,
                           const float* __restrict__ m, const float* __restrict__ v) {
    int idx = blockIdx.x * blockDim.x + threadIdx.x;
    const int total = N_NODES * (F_IN / 4);
    if (idx >= total) return;
    int c = (idx & (F_IN / 4 - 1)) * 4;
    float4 xv = x[idx];
    float4 o;
    o.x = (xv.x - __ldg(m + c + 0)) * (__ldg(g + c + 0) * rsqrtf(__ldg(v + c + 0) + BN_EPS)) + __ldg(b + c + 0);
    o.y = (xv.y - __ldg(m + c + 1)) * (__ldg(g + c + 1) * rsqrtf(__ldg(v + c + 1) + BN_EPS)) + __ldg(b + c + 1);
    o.z = (xv.z - __ldg(m + c + 2)) * (__ldg(g + c + 2) * rsqrtf(__ldg(v + c + 2) + BN_EPS)) + __ldg(b + c + 2);
    o.w = (xv.w - __ldg(m + c + 3)) * (__ldg(g + c + 3) * rsqrtf(__ldg(v + c + 3) + BN_EPS)) + __ldg(b + c + 3);
    ((float4*)g_h0)[idx] = o;
    ((float4*)g_agg1)[idx] = o;
}

// ---------------------------------------------------------------------------
// K2: edge scatter-add, F=128. One warp per edge; lane does one v4 reduction.
// ---------------------------------------------------------------------------
__global__ void scatter128_kernel(const int* __restrict__ src,
                                  const int* __restrict__ dst) {
    int t = blockIdx.x * blockDim.x + threadIdx.x;
    int e = t >> 5;
    if (e >= N_EDGES) return;
    int lane = t & 31;
    int s = clamp_idx(__ldg(src + e));
    int d = clamp_idx(__ldg(dst + e));
    float4 hv = ((const float4*)(g_h0 + (size_t)s * F_IN))[lane];
    float* dp = g_agg1 + (size_t)d * F_IN + lane * 4;
    red_add_v4(dp, hv);
}

// ---------------------------------------------------------------------------
// K3: GEMM1 [50000,128]x[128,256] + bias + BN1 + ReLU -> g_h1.
//     64x64 tile, 256 threads, 4x4 per thread.  (R7 proven config)
// ---------------------------------------------------------------------------
__global__ void gemm1_kernel(const float* __restrict__ W1, const float* __restrict__ b1,
                             const float* __restrict__ bg, const float* __restrict__ bb,
                             const float* __restrict__ bm, const float* __restrict__ bv) {
    __shared__ __align__(16) float sA[64][68];
    __shared__ __align__(16) float sB[64][68];
    const float* A = g_agg1;
    int tid = threadIdx.x;
    int block_m = blockIdx.x * 64;
    int block_n = blockIdx.y * 64;
    int tx = tid & 15, ty = tid >> 4;

    float acc[4][4];
#pragma unroll
    for (int i = 0; i < 4; i++)
#pragma unroll
        for (int j = 0; j < 4; j++) acc[i][j] = 0.f;

    for (int kk = 0; kk < F_IN; kk += 64) {
#pragma unroll
        for (int i = 0; i < 4; i++) {
            int f4 = tid + i * 256;
            int row = f4 >> 4;
            int c4 = f4 & 15;
            int gr = block_m + row;
            float4 val = make_float4(0.f, 0.f, 0.f, 0.f);
            if (gr < N_NODES)
                val = ((const float4*)(A + (size_t)gr * F_IN + kk))[c4];
            *(float4*)&sA[row][c4 * 4] = val;
        }
#pragma unroll
        for (int i = 0; i < 4; i++) {
            int f4 = tid + i * 256;
            int k = f4 >> 4;
            int c4 = f4 & 15;
            float4 val = ((const float4*)(W1 + (size_t)(kk + k) * HID + block_n))[c4];
            *(float4*)&sB[k][c4 * 4] = val;
        }
        __syncthreads();

#pragma unroll
        for (int k = 0; k < 64; k++) {
            float a[4], bvreg[4];
#pragma unroll
            for (int i = 0; i < 4; i++) a[i] = sA[ty * 4 + i][k];
#pragma unroll
            for (int j = 0; j < 4; j++) bvreg[j] = sB[k][tx * 4 + j];
#pragma unroll
            for (int i = 0; i < 4; i++)
#pragma unroll
                for (int j = 0; j < 4; j++) acc[i][j] += a[i] * bvreg[j];
        }
        __syncthreads();
    }

#pragma unroll
    for (int j = 0; j < 4; j++) {
        int c = block_n + tx * 4 + j;
        float s = __ldg(bg + c) * rsqrtf(__ldg(bv + c) + BN_EPS);
        float mu = __ldg(bm + c);
        float be = __ldg(bb + c);
        float bias = __ldg(b1 + c);
#pragma unroll
        for (int i = 0; i < 4; i++) {
            int gr = block_m + ty * 4 + i;
            if (gr < N_NODES) {
                float val = acc[i][j] + bias;
                val = (val - mu) * s + be;
                val = fmaxf(val, 0.f);
                g_h1[(size_t)gr * HID + c] = val;
            }
        }
    }
}

// ---------------------------------------------------------------------------
// K4: GEMM2 [50000,256]x[256,40] tiled. BM=128, BN=40, BK=32, 4x5/thread.
//     Double-buffered smem + register prefetch, one barrier per k-iter.
// ---------------------------------------------------------------------------
__global__ void __launch_bounds__(256)
gemm2_kernel(const float* __restrict__ W2, const float* __restrict__ b2,
             float* __restrict__ out) {
    __shared__ float sA[2][128][33];     // [buf][row][k]
    __shared__ float sB[2][32][41];      // [buf][k][col]
    int tid = threadIdx.x;
    int tx = tid & 7;                    // 0..7  -> 5 cols each
    int ty = tid >> 3;                   // 0..31 -> 4 rows each
    int block_m = blockIdx.x * 128;

    // Per-thread load coordinates (fixed across iterations)
    int a_row[4], a_c4[4];
#pragma unroll
    for (int i = 0; i < 4; i++) {
        int f4 = tid + i * 256;          // 0..1023
        a_row[i] = f4 >> 3;              // 0..127
        a_c4[i] = f4 & 7;                // 0..7
    }
    int b_k[5], b_c[5];
#pragma unroll
    for (int i = 0; i < 5; i++) {
        int idx = tid + i * 256;         // 0..1279
        b_k[i] = idx / NCLS;
        b_c[i] = idx - b_k[i] * NCLS;
    }

    float4 pa[4];
    float pb[5];

    // Prologue: load k-block 0 into regs, store to buffer 0
#pragma unroll
    for (int i = 0; i < 4; i++) {
        int gr = block_m + a_row[i];
        pa[i] = make_float4(0.f, 0.f, 0.f, 0.f);
        if (gr < N_NODES)
            pa[i] = ((const float4*)(g_h1 + (size_t)gr * HID))[a_c4[i]];
    }
#pragma unroll
    for (int i = 0; i < 5; i++)
        pb[i] = W2[(size_t)b_k[i] * NCLS + b_c[i]];
#pragma unroll
    for (int i = 0; i < 4; i++) {
        sA[0][a_row[i]][a_c4[i] * 4 + 0] = pa[i].x;
        sA[0][a_row[i]][a_c4[i] * 4 + 1] = pa[i].y;
        sA[0][a_row[i]][a_c4[i] * 4 + 2] = pa[i].z;
        sA[0][a_row[i]][a_c4[i] * 4 + 3] = pa[i].w;
    }
#pragma unroll
    for (int i = 0; i < 5; i++)
        sB[0][b_k[i]][b_c[i]] = pb[i];
    __syncthreads();

    float acc[4][5];
#pragma unroll
    for (int i = 0; i < 4; i++)
#pragma unroll
        for (int j = 0; j < 5; j++) acc[i][j] = 0.f;

    const int NITER = HID / 32;          // 8
#pragma unroll
    for (int it = 0; it < NITER; it++) {
        int p = it & 1;
        // Prefetch next k-block into registers (overlaps with compute below)
        if (it < NITER - 1) {
            int kk = (it + 1) * 32;
#pragma unroll
            for (int i = 0; i < 4; i++) {
                int gr = block_m + a_row[i];
                pa[i] = make_float4(0.f, 0.f, 0.f, 0.f);
                if (gr < N_NODES)
                    pa[i] = ((const float4*)(g_h1 + (size_t)gr * HID + kk))[a_c4[i]];
            }
#pragma unroll
            for (int i = 0; i < 5; i++)
                pb[i] = W2[(size_t)(kk + b_k[i]) * NCLS + b_c[i]];
        }

        // Compute on buffer p
#pragma unroll
        for (int k = 0; k < 32; k++) {
            float a[4], bv[5];
#pragma unroll
            for (int i = 0; i < 4; i++) a[i] = sA[p][ty * 4 + i][k];
#pragma unroll
            for (int j = 0; j < 5; j++) bv[j] = sB[p][k][tx * 5 + j];
#pragma unroll
            for (int i = 0; i < 4; i++)
#pragma unroll
                for (int j = 0; j < 5; j++) acc[i][j] += a[i] * bv[j];
        }

        // Store prefetched regs into the other buffer, one barrier per iter
        if (it < NITER - 1) {
            int q = 1 - p;
#pragma unroll
            for (int i = 0; i < 4; i++) {
                sA[q][a_row[i]][a_c4[i] * 4 + 0] = pa[i].x;
                sA[q][a_row[i]][a_c4[i] * 4 + 1] = pa[i].y;
                sA[q][a_row[i]][a_c4[i] * 4 + 2] = pa[i].z;
                sA[q][a_row[i]][a_c4[i] * 4 + 3] = pa[i].w;
            }
#pragma unroll
            for (int i = 0; i < 5; i++)
                sB[q][b_k[i]][b_c[i]] = pb[i];
            __syncthreads();
        }
    }

    // Epilogue: z -> g_z; z + b2 -> out
    float bias[5];
#pragma unroll
    for (int j = 0; j < 5; j++) bias[j] = __ldg(b2 + tx * 5 + j);
#pragma unroll
    for (int i = 0; i < 4; i++) {
        int gr = block_m + ty * 4 + i;
        if (gr < N_NODES) {
            float* zp = g_z + (size_t)gr * NCLS + tx * 5;
            float* op = out + (size_t)gr * NCLS + tx * 5;
#pragma unroll
            for (int j = 0; j < 5; j++) {
                zp[j] = acc[i][j];
                op[j] = acc[i][j] + bias[j];
            }
        }
    }
}

// ---------------------------------------------------------------------------
// K5: edge scatter-add in logit space (40 floats/edge = 10 float4 chunks).
//     out[dst] += z[src]. Thread = (edge, chunk).
// ---------------------------------------------------------------------------
__global__ void scatter40_kernel(const int* __restrict__ src,
                                 const int* __restrict__ dst,
                                 float* __restrict__ out) {
    int t = blockIdx.x * blockDim.x + threadIdx.x;
    int e = t / (NCLS / 4);
    if (e >= N_EDGES) return;
    int chunk = t - e * (NCLS / 4);
    int s = clamp_idx(__ldg(src + e));
    int d = clamp_idx(__ldg(dst + e));
    float4 v = *(const float4*)(g_z + (size_t)s * NCLS + chunk * 4);
    float* p = out + (size_t)d * NCLS + chunk * 4;
    red_add_v4(p, v);
}

// ---------------------------------------------------------------------------
extern "C" void kernel_launch(void* const* d_in, const int* in_sizes, int n_in,
                              void* d_out, int out_size) {
    const float* x = (const float*)d_in[0];
    const int* ei = (const int*)d_in[1];   // int32 (jax x64-disabled)
    const float* bn0g = (const float*)d_in[2];
    const float* bn0b = (const float*)d_in[3];
    const float* bn0m = (const float*)d_in[4];
    const float* bn0v = (const float*)d_in[5];
    const float* W1 = (const float*)d_in[6];
    const float* b1 = (const float*)d_in[7];
    const float* bn1g = (const float*)d_in[8];
    const float* bn1b = (const float*)d_in[9];
    const float* bn1m = (const float*)d_in[10];
    const float* bn1v = (const float*)d_in[11];
    const float* W2 = (const float*)d_in[12];
    const float* b2 = (const float*)d_in[13];
    float* out = (float*)d_out;

    const int* src = ei;
    const int* dst = ei + N_EDGES;

    // K1: BN0 -> g_h0, g_agg1
    {
        int total = N_NODES * (F_IN / 4);
        bn0_kernel<<<(total + 255) / 256, 256>>>((const float4*)x, bn0g, bn0b, bn0m, bn0v);
    }
    // K2: 128-dim scatter-add into g_agg1 (v4 reductions)
    {
        long long threads = (long long)N_EDGES * 32;
        scatter128_kernel<<<(int)((threads + 255) / 256), 256>>>(src, dst);
    }
    // K3: GEMM1 + BN1 + ReLU -> g_h1
    {
        dim3 grid((N_NODES + 63) / 64, HID / 64);
        gemm1_kernel<<<grid, 256>>>(W1, b1, bn1g, bn1b, bn1m, bn1v);
    }
    // K4: GEMM2 (double-buffered) -> g_z, out = z + b2
    {
        gemm2_kernel<<<(N_NODES + 127) / 128, 256>>>(W2, b2, out);
    }
    // K5: 40-dim scatter-add into out (associativity: (h+Ah)W = hW + A(hW))
    {
        long long threads = (long long)N_EDGES * (NCLS / 4);
        scatter40_kernel<<<(int)((threads + 255) / 256), 256>>>(src, dst, out);
    }
}

// round 10
// speedup vs baseline: 1.4599x; 1.4135x over previous
#include <cuda_runtime.h>
#include <math.h>
#include <stdint.h>

#define N_NODES 50000
#define F_IN 128
#define HID 256
#define NCLS 40
#define N_EDGES 600000
#define BN_EPS 1e-5f

// Scratch (static device globals -- no runtime allocation allowed)
__device__ float g_h0[N_NODES * F_IN];    // BN0(x)
__device__ float g_agg1[N_NODES * F_IN];  // h0 + scatter
__device__ float g_h1[N_NODES * HID];     // relu(BN1(agg1 @ W1 + b1))
__device__ float g_z[N_NODES * NCLS];     // h1 @ W2 (pre-aggregation logits)

__device__ __forceinline__ int clamp_idx(int i) {
    i = i < 0 ? 0 : i;
    return i >= N_NODES ? N_NODES - 1 : i;
}

__device__ __forceinline__ void red_add_v4(float* p, float4 v) {
    asm volatile("red.global.add.v4.f32 [%0], {%1, %2, %3, %4};"
                 :: "l"(p), "f"(v.x), "f"(v.y), "f"(v.z), "f"(v.w)
                 : "memory");
}

// Round-to-nearest f32 -> tf32 (kept in 32-bit container)
__device__ __forceinline__ unsigned tf32r(float x) {
    unsigned r;
    asm("cvt.rna.tf32.f32 %0, %1;" : "=r"(r) : "f"(x));
    return r;
}

// D += A*B for one m16n8k8 tf32 tile
__device__ __forceinline__ void mma_tf32(float* d, const unsigned* a, const unsigned* b) {
    asm volatile(
        "mma.sync.aligned.m16n8k8.row.col.f32.tf32.tf32.f32 "
        "{%0,%1,%2,%3}, {%4,%5,%6,%7}, {%8,%9}, {%0,%1,%2,%3};"
        : "+f"(d[0]), "+f"(d[1]), "+f"(d[2]), "+f"(d[3])
        : "r"(a[0]), "r"(a[1]), "r"(a[2]), "r"(a[3]), "r"(b[0]), "r"(b[1]));
}

// ---------------------------------------------------------------------------
// K1: BN0 over input features; writes g_h0 and initializes g_agg1 (self term)
// ---------------------------------------------------------------------------
__global__ void bn0_kernel(const float4* __restrict__ x,
                           const float* __restrict__ g, const float* __restrict__ b,
                           const float* __restrict__ m, const float* __restrict__ v) {
    int idx = blockIdx.x * blockDim.x + threadIdx.x;
    const int total = N_NODES * (F_IN / 4);
    if (idx >= total) return;
    int c = (idx & (F_IN / 4 - 1)) * 4;
    float4 xv = x[idx];
    float4 o;
    o.x = (xv.x - __ldg(m + c + 0)) * (__ldg(g + c + 0) * rsqrtf(__ldg(v + c + 0) + BN_EPS)) + __ldg(b + c + 0);
    o.y = (xv.y - __ldg(m + c + 1)) * (__ldg(g + c + 1) * rsqrtf(__ldg(v + c + 1) + BN_EPS)) + __ldg(b + c + 1);
    o.z = (xv.z - __ldg(m + c + 2)) * (__ldg(g + c + 2) * rsqrtf(__ldg(v + c + 2) + BN_EPS)) + __ldg(b + c + 2);
    o.w = (xv.w - __ldg(m + c + 3)) * (__ldg(g + c + 3) * rsqrtf(__ldg(v + c + 3) + BN_EPS)) + __ldg(b + c + 3);
    ((float4*)g_h0)[idx] = o;
    ((float4*)g_agg1)[idx] = o;
}

// ---------------------------------------------------------------------------
// K2: edge scatter-add, F=128. One warp per edge; lane does one v4 reduction.
// ---------------------------------------------------------------------------
__global__ void scatter128_kernel(const int* __restrict__ src,
                                  const int* __restrict__ dst) {
    int t = blockIdx.x * blockDim.x + threadIdx.x;
    int e = t >> 5;
    if (e >= N_EDGES) return;
    int lane = t & 31;
    int s = clamp_idx(__ldg(src + e));
    int d = clamp_idx(__ldg(dst + e));
    float4 hv = ((const float4*)(g_h0 + (size_t)s * F_IN))[lane];
    float* dp = g_agg1 + (size_t)d * F_IN + lane * 4;
    red_add_v4(dp, hv);
}

// ---------------------------------------------------------------------------
// K3: GEMM1 [50000,128]x[128,256] + bias + BN1 + ReLU -> g_h1.
//     TF32 mma.sync m16n8k8. CTA tile 128x64, 8 warps (2m x 4n),
//     warp tile 64x16 (4 m-tiles x 2 n-tiles), K chunk 32.
// ---------------------------------------------------------------------------
__global__ void __launch_bounds__(256)
gemm1_kernel(const float* __restrict__ W1, const float* __restrict__ b1,
             const float* __restrict__ bg, const float* __restrict__ bb,
             const float* __restrict__ bm, const float* __restrict__ bv) {
    __shared__ unsigned sA[128][36];   // [m][k], stride 36 -> conflict-free frags
    __shared__ unsigned sB[32][72];    // [k][n], stride 72 -> conflict-free frags
    int tid = threadIdx.x;
    int warp = tid >> 5, lane = tid & 31;
    int wm = warp >> 2;                // 0..1
    int wn = warp & 3;                 // 0..3
    int gq = lane >> 2, tg = lane & 3; // group / thread-in-group
    int block_m = blockIdx.x * 128;
    int block_n = blockIdx.y * 64;

    float acc[4][2][4];
#pragma unroll
    for (int mt = 0; mt < 4; mt++)
#pragma unroll
        for (int nt = 0; nt < 2; nt++)
#pragma unroll
            for (int r = 0; r < 4; r++) acc[mt][nt][r] = 0.f;

    for (int kk = 0; kk < F_IN; kk += 32) {
        // Load A tile: 128 rows x 32 k = 1024 float4; 4 per thread
#pragma unroll
        for (int i = 0; i < 4; i++) {
            int f4 = tid + i * 256;      // 0..1023
            int row = f4 >> 3;           // 0..127
            int c4 = f4 & 7;             // 0..7
            int gr = block_m + row;
            float4 v = make_float4(0.f, 0.f, 0.f, 0.f);
            if (gr < N_NODES)
                v = ((const float4*)(g_agg1 + (size_t)gr * F_IN + kk))[c4];
            sA[row][c4 * 4 + 0] = tf32r(v.x);
            sA[row][c4 * 4 + 1] = tf32r(v.y);
            sA[row][c4 * 4 + 2] = tf32r(v.z);
            sA[row][c4 * 4 + 3] = tf32r(v.w);
        }
        // Load B tile: W1 rows kk..kk+31, cols block_n..+63 = 512 float4; 2/thread
#pragma unroll
        for (int i = 0; i < 2; i++) {
            int f4 = tid + i * 256;      // 0..511
            int k = f4 >> 4;             // 0..31
            int c4 = f4 & 15;            // 0..15
            float4 v = ((const float4*)(W1 + (size_t)(kk + k) * HID + block_n))[c4];
            sB[k][c4 * 4 + 0] = tf32r(v.x);
            sB[k][c4 * 4 + 1] = tf32r(v.y);
            sB[k][c4 * 4 + 2] = tf32r(v.z);
            sB[k][c4 * 4 + 3] = tf32r(v.w);
        }
        __syncthreads();

#pragma unroll
        for (int k8 = 0; k8 < 4; k8++) {
            int kb = k8 * 8;
            unsigned afr[4][4];
#pragma unroll
            for (int mt = 0; mt < 4; mt++) {
                int r = wm * 64 + mt * 16;
                afr[mt][0] = sA[r + gq][kb + tg];
                afr[mt][1] = sA[r + gq + 8][kb + tg];
                afr[mt][2] = sA[r + gq][kb + tg + 4];
                afr[mt][3] = sA[r + gq + 8][kb + tg + 4];
            }
            unsigned bfr[2][2];
#pragma unroll
            for (int nt = 0; nt < 2; nt++) {
                int c = wn * 16 + nt * 8 + gq;
                bfr[nt][0] = sB[kb + tg][c];
                bfr[nt][1] = sB[kb + tg + 4][c];
            }
#pragma unroll
            for (int mt = 0; mt < 4; mt++)
#pragma unroll
                for (int nt = 0; nt < 2; nt++)
                    mma_tf32(acc[mt][nt], afr[mt], bfr[nt]);
        }
        __syncthreads();
    }

    // Epilogue: + bias, BN1 (eval), ReLU -> g_h1
#pragma unroll
    for (int nt = 0; nt < 2; nt++) {
        int c0 = block_n + wn * 16 + nt * 8 + tg * 2;
        float s0 = __ldg(bg + c0) * rsqrtf(__ldg(bv + c0) + BN_EPS);
        float s1 = __ldg(bg + c0 + 1) * rsqrtf(__ldg(bv + c0 + 1) + BN_EPS);
        float mu0 = __ldg(bm + c0), mu1 = __ldg(bm + c0 + 1);
        float be0 = __ldg(bb + c0), be1 = __ldg(bb + c0 + 1);
        float bi0 = __ldg(b1 + c0), bi1 = __ldg(b1 + c0 + 1);
#pragma unroll
        for (int mt = 0; mt < 4; mt++) {
            int r0 = block_m + wm * 64 + mt * 16 + gq;
#pragma unroll
            for (int h = 0; h < 2; h++) {
                int r = r0 + h * 8;
                if (r < N_NODES) {
                    float v0 = acc[mt][nt][h * 2 + 0] + bi0;
                    float v1 = acc[mt][nt][h * 2 + 1] + bi1;
                    v0 = fmaxf((v0 - mu0) * s0 + be0, 0.f);
                    v1 = fmaxf((v1 - mu1) * s1 + be1, 0.f);
                    g_h1[(size_t)r * HID + c0] = v0;
                    g_h1[(size_t)r * HID + c0 + 1] = v1;
                }
            }
        }
    }
}

// ---------------------------------------------------------------------------
// K4: GEMM2 [50000,256]x[256,40] TF32 mma. CTA tile 128x40, 8 warps,
//     each warp: 1 m16 tile x 5 n8 tiles. K chunk 32.
//     Writes z to g_z and z + b2 (self term) to out.
// ---------------------------------------------------------------------------
__global__ void __launch_bounds__(256)
gemm2_kernel(const float* __restrict__ W2, const float* __restrict__ b2,
             float* __restrict__ out) {
    __shared__ unsigned sA[128][36];   // [m][k]
    __shared__ unsigned sB[32][44];    // [k][n], stride 44 -> conflict-free
    int tid = threadIdx.x;
    int warp = tid >> 5, lane = tid & 31;
    int gq = lane >> 2, tg = lane & 3;
    int block_m = blockIdx.x * 128;

    float acc[5][4];
#pragma unroll
    for (int nt = 0; nt < 5; nt++)
#pragma unroll
        for (int r = 0; r < 4; r++) acc[nt][r] = 0.f;

    for (int kk = 0; kk < HID; kk += 32) {
        // A tile: 128 rows x 32 k = 1024 float4; 4/thread
#pragma unroll
        for (int i = 0; i < 4; i++) {
            int f4 = tid + i * 256;
            int row = f4 >> 3;
            int c4 = f4 & 7;
            int gr = block_m + row;
            float4 v = make_float4(0.f, 0.f, 0.f, 0.f);
            if (gr < N_NODES)
                v = ((const float4*)(g_h1 + (size_t)gr * HID + kk))[c4];
            sA[row][c4 * 4 + 0] = tf32r(v.x);
            sA[row][c4 * 4 + 1] = tf32r(v.y);
            sA[row][c4 * 4 + 2] = tf32r(v.z);
            sA[row][c4 * 4 + 3] = tf32r(v.w);
        }
        // B tile: 32 k x 40 cols = 1280 floats; 5 scalars/thread
#pragma unroll
        for (int i = 0; i < 5; i++) {
            int idx = tid + i * 256;
            int k = idx / NCLS;
            int c = idx - k * NCLS;
            sB[k][c] = tf32r(W2[(size_t)(kk + k) * NCLS + c]);
        }
        __syncthreads();

#pragma unroll
        for (int k8 = 0; k8 < 4; k8++) {
            int kb = k8 * 8;
            unsigned afr[4];
            int r = warp * 16;
            afr[0] = sA[r + gq][kb + tg];
            afr[1] = sA[r + gq + 8][kb + tg];
            afr[2] = sA[r + gq][kb + tg + 4];
            afr[3] = sA[r + gq + 8][kb + tg + 4];
#pragma unroll
            for (int nt = 0; nt < 5; nt++) {
                unsigned bfr[2];
                int c = nt * 8 + gq;
                bfr[0] = sB[kb + tg][c];
                bfr[1] = sB[kb + tg + 4][c];
                mma_tf32(acc[nt], afr, bfr);
            }
        }
        __syncthreads();
    }

    // Epilogue: z -> g_z; z + b2 -> out
#pragma unroll
    for (int nt = 0; nt < 5; nt++) {
        int c0 = nt * 8 + tg * 2;
        float bi0 = __ldg(b2 + c0), bi1 = __ldg(b2 + c0 + 1);
        int r0 = block_m + warp * 16 + gq;
#pragma unroll
        for (int h = 0; h < 2; h++) {
            int r = r0 + h * 8;
            if (r < N_NODES) {
                float v0 = acc[nt][h * 2 + 0];
                float v1 = acc[nt][h * 2 + 1];
                g_z[(size_t)r * NCLS + c0] = v0;
                g_z[(size_t)r * NCLS + c0 + 1] = v1;
                out[(size_t)r * NCLS + c0] = v0 + bi0;
                out[(size_t)r * NCLS + c0 + 1] = v1 + bi1;
            }
        }
    }
}

// ---------------------------------------------------------------------------
// K5: edge scatter-add in logit space (40 floats/edge = 10 float4 chunks).
//     out[dst] += z[src]. Thread = (edge, chunk).
// ---------------------------------------------------------------------------
__global__ void scatter40_kernel(const int* __restrict__ src,
                                 const int* __restrict__ dst,
                                 float* __restrict__ out) {
    int t = blockIdx.x * blockDim.x + threadIdx.x;
    int e = t / (NCLS / 4);
    if (e >= N_EDGES) return;
    int chunk = t - e * (NCLS / 4);
    int s = clamp_idx(__ldg(src + e));
    int d = clamp_idx(__ldg(dst + e));
    float4 v = *(const float4*)(g_z + (size_t)s * NCLS + chunk * 4);
    float* p = out + (size_t)d * NCLS + chunk * 4;
    red_add_v4(p, v);
}

// ---------------------------------------------------------------------------
extern "C" void kernel_launch(void* const* d_in, const int* in_sizes, int n_in,
                              void* d_out, int out_size) {
    const float* x = (const float*)d_in[0];
    const int* ei = (const int*)d_in[1];   // int32 (jax x64-disabled)
    const float* bn0g = (const float*)d_in[2];
    const float* bn0b = (const float*)d_in[3];
    const float* bn0m = (const float*)d_in[4];
    const float* bn0v = (const float*)d_in[5];
    const float* W1 = (const float*)d_in[6];
    const float* b1 = (const float*)d_in[7];
    const float* bn1g = (const float*)d_in[8];
    const float* bn1b = (const float*)d_in[9];
    const float* bn1m = (const float*)d_in[10];
    const float* bn1v = (const float*)d_in[11];
    const float* W2 = (const float*)d_in[12];
    const float* b2 = (const float*)d_in[13];
    float* out = (float*)d_out;

    const int* src = ei;
    const int* dst = ei + N_EDGES;

    // K1: BN0 -> g_h0, g_agg1
    {
        int total = N_NODES * (F_IN / 4);
        bn0_kernel<<<(total + 255) / 256, 256>>>((const float4*)x, bn0g, bn0b, bn0m, bn0v);
    }
    // K2: 128-dim scatter-add into g_agg1 (v4 reductions)
    {
        long long threads = (long long)N_EDGES * 32;
        scatter128_kernel<<<(int)((threads + 255) / 256), 256>>>(src, dst);
    }
    // K3: GEMM1 (tf32 mma) + BN1 + ReLU -> g_h1
    {
        dim3 grid((N_NODES + 127) / 128, HID / 64);
        gemm1_kernel<<<grid, 256>>>(W1, b1, bn1g, bn1b, bn1m, bn1v);
    }
    // K4: GEMM2 (tf32 mma) -> g_z, out = z + b2
    {
        gemm2_kernel<<<(N_NODES + 127) / 128, 256>>>(W2, b2, out);
    }
    // K5: 40-dim scatter-add into out (associativity: (h+Ah)W = hW + A(hW))
    {
        long long threads = (long long)N_EDGES * (NCLS / 4);
        scatter40_kernel<<<(int)((threads + 255) / 256), 256>>>(src, dst, out);
    }
}

// round 11
// speedup vs baseline: 1.5447x; 1.0581x over previous
#include <cuda_runtime.h>
#include <math.h>
#include <stdint.h>

#define N_NODES 50000
#define F_IN 128
#define HID 256
#define NCLS 40
#define N_EDGES 600000
#define BN_EPS 1e-5f

// Scratch (static device globals -- no runtime allocation allowed)
__device__ float g_h0[N_NODES * F_IN];    // BN0(x)
__device__ float g_agg1[N_NODES * F_IN];  // h0 + scatter
__device__ float g_h1[N_NODES * HID];     // relu(BN1(...)), tf32-rounded values
__device__ float g_z[N_NODES * NCLS];     // h1 @ W2 (pre-aggregation logits)
__device__ float g_w1tf[F_IN * HID];      // W1 pre-rounded to tf32
__device__ float g_w2tf[HID * NCLS];      // W2 pre-rounded to tf32

__device__ __forceinline__ int clamp_idx(int i) {
    i = i < 0 ? 0 : i;
    return i >= N_NODES ? N_NODES - 1 : i;
}

__device__ __forceinline__ void red_add_v4(float* p, float4 v) {
    asm volatile("red.global.add.v4.f32 [%0], {%1, %2, %3, %4};"
                 :: "l"(p), "f"(v.x), "f"(v.y), "f"(v.z), "f"(v.w)
                 : "memory");
}

// Round-to-nearest f32 -> tf32 (kept in 32-bit container)
__device__ __forceinline__ unsigned tf32r(float x) {
    unsigned r;
    asm("cvt.rna.tf32.f32 %0, %1;" : "=r"(r) : "f"(x));
    return r;
}

// D += A*B for one m16n8k8 tf32 tile
__device__ __forceinline__ void mma_tf32(float* d, const unsigned* a, const unsigned* b) {
    asm volatile(
        "mma.sync.aligned.m16n8k8.row.col.f32.tf32.tf32.f32 "
        "{%0,%1,%2,%3}, {%4,%5,%6,%7}, {%8,%9}, {%0,%1,%2,%3};"
        : "+f"(d[0]), "+f"(d[1]), "+f"(d[2]), "+f"(d[3])
        : "r"(a[0]), "r"(a[1]), "r"(a[2]), "r"(a[3]), "r"(b[0]), "r"(b[1]));
}

__device__ __forceinline__ void cp_async16(uint32_t saddr, const void* gptr, int sz) {
    asm volatile("cp.async.cg.shared.global [%0], [%1], 16, %2;"
                 :: "r"(saddr), "l"(gptr), "r"(sz) : "memory");
}
__device__ __forceinline__ void cp_commit() {
    asm volatile("cp.async.commit_group;" ::: "memory");
}
template <int N>
__device__ __forceinline__ void cp_wait() {
    asm volatile("cp.async.wait_group %0;" :: "n"(N) : "memory");
}
__device__ __forceinline__ uint32_t smem_u32(const void* p) {
    return (uint32_t)__cvta_generic_to_shared(p);
}

// ---------------------------------------------------------------------------
// K0: one-time weight pre-rounding to tf32
// ---------------------------------------------------------------------------
__global__ void convert_w_kernel(const float* __restrict__ W1,
                                 const float* __restrict__ W2) {
    int i = blockIdx.x * blockDim.x + threadIdx.x;
    if (i < F_IN * HID) g_w1tf[i] = __uint_as_float(tf32r(W1[i]));
    if (i < HID * NCLS) g_w2tf[i] = __uint_as_float(tf32r(W2[i]));
}

// ---------------------------------------------------------------------------
// K1: BN0 over input features; writes g_h0 and initializes g_agg1 (self term)
// ---------------------------------------------------------------------------
__global__ void bn0_kernel(const float4* __restrict__ x,
                           const float* __restrict__ g, const float* __restrict__ b,
                           const float* __restrict__ m, const float* __restrict__ v) {
    int idx = blockIdx.x * blockDim.x + threadIdx.x;
    const int total = N_NODES * (F_IN / 4);
    if (idx >= total) return;
    int c = (idx & (F_IN / 4 - 1)) * 4;
    float4 xv = x[idx];
    float4 o;
    o.x = (xv.x - __ldg(m + c + 0)) * (__ldg(g + c + 0) * rsqrtf(__ldg(v + c + 0) + BN_EPS)) + __ldg(b + c + 0);
    o.y = (xv.y - __ldg(m + c + 1)) * (__ldg(g + c + 1) * rsqrtf(__ldg(v + c + 1) + BN_EPS)) + __ldg(b + c + 1);
    o.z = (xv.z - __ldg(m + c + 2)) * (__ldg(g + c + 2) * rsqrtf(__ldg(v + c + 2) + BN_EPS)) + __ldg(b + c + 2);
    o.w = (xv.w - __ldg(m + c + 3)) * (__ldg(g + c + 3) * rsqrtf(__ldg(v + c + 3) + BN_EPS)) + __ldg(b + c + 3);
    ((float4*)g_h0)[idx] = o;
    ((float4*)g_agg1)[idx] = o;
}

// ---------------------------------------------------------------------------
// K2: edge scatter-add, F=128. One warp per edge; lane does one v4 reduction.
// ---------------------------------------------------------------------------
__global__ void scatter128_kernel(const int* __restrict__ src,
                                  const int* __restrict__ dst) {
    int t = blockIdx.x * blockDim.x + threadIdx.x;
    int e = t >> 5;
    if (e >= N_EDGES) return;
    int lane = t & 31;
    int s = clamp_idx(__ldg(src + e));
    int d = clamp_idx(__ldg(dst + e));
    float4 hv = ((const float4*)(g_h0 + (size_t)s * F_IN))[lane];
    float* dp = g_agg1 + (size_t)d * F_IN + lane * 4;
    red_add_v4(dp, hv);
}

// ---------------------------------------------------------------------------
// K3: GEMM1 [50000,128]x[128,256] + bias + BN1 + ReLU -> g_h1 (tf32-rounded).
//     TF32 mma m16n8k8. CTA 128x128, 8 warps (2m x 4n), warp tile 64x32.
// ---------------------------------------------------------------------------
__global__ void __launch_bounds__(256)
gemm1_kernel(const float* __restrict__ b1,
             const float* __restrict__ bg, const float* __restrict__ bb,
             const float* __restrict__ bm, const float* __restrict__ bv) {
    __shared__ __align__(16) unsigned sA[128][36];   // [m][k], frag reads conflict-free
    __shared__ __align__(16) unsigned sB[32][136];   // [k][n], 136%32=8 -> conflict-free
    int tid = threadIdx.x;
    int warp = tid >> 5, lane = tid & 31;
    int wm = warp >> 2;                // 0..1
    int wn = warp & 3;                 // 0..3
    int gq = lane >> 2, tg = lane & 3;
    int block_m = blockIdx.x * 128;
    int block_n = blockIdx.y * 128;

    float acc[4][4][4];
#pragma unroll
    for (int mt = 0; mt < 4; mt++)
#pragma unroll
        for (int nt = 0; nt < 4; nt++)
#pragma unroll
            for (int r = 0; r < 4; r++) acc[mt][nt][r] = 0.f;

    for (int kk = 0; kk < F_IN; kk += 32) {
        // A tile: 128 rows x 32 k = 1024 float4; 4/thread, with cvt
#pragma unroll
        for (int i = 0; i < 4; i++) {
            int f4 = tid + i * 256;
            int row = f4 >> 3;
            int c4 = f4 & 7;
            int gr = block_m + row;
            float4 v = make_float4(0.f, 0.f, 0.f, 0.f);
            if (gr < N_NODES)
                v = ((const float4*)(g_agg1 + (size_t)gr * F_IN + kk))[c4];
            sA[row][c4 * 4 + 0] = tf32r(v.x);
            sA[row][c4 * 4 + 1] = tf32r(v.y);
            sA[row][c4 * 4 + 2] = tf32r(v.z);
            sA[row][c4 * 4 + 3] = tf32r(v.w);
        }
        // B tile: pre-rounded g_w1tf rows kk..kk+31, cols block_n..+127.
        // 1024 float4; 4/thread, raw copy.
#pragma unroll
        for (int i = 0; i < 4; i++) {
            int f4 = tid + i * 256;
            int k = f4 >> 5;             // 0..31
            int c4 = f4 & 31;            // 0..31
            float4 v = ((const float4*)(g_w1tf + (size_t)(kk + k) * HID + block_n))[c4];
            sB[k][c4 * 4 + 0] = __float_as_uint(v.x);
            sB[k][c4 * 4 + 1] = __float_as_uint(v.y);
            sB[k][c4 * 4 + 2] = __float_as_uint(v.z);
            sB[k][c4 * 4 + 3] = __float_as_uint(v.w);
        }
        __syncthreads();

#pragma unroll
        for (int k8 = 0; k8 < 4; k8++) {
            int kb = k8 * 8;
            unsigned afr[4][4];
#pragma unroll
            for (int mt = 0; mt < 4; mt++) {
                int r = wm * 64 + mt * 16;
                afr[mt][0] = sA[r + gq][kb + tg];
                afr[mt][1] = sA[r + gq + 8][kb + tg];
                afr[mt][2] = sA[r + gq][kb + tg + 4];
                afr[mt][3] = sA[r + gq + 8][kb + tg + 4];
            }
            unsigned bfr[4][2];
#pragma unroll
            for (int nt = 0; nt < 4; nt++) {
                int c = wn * 32 + nt * 8 + gq;
                bfr[nt][0] = sB[kb + tg][c];
                bfr[nt][1] = sB[kb + tg + 4][c];
            }
#pragma unroll
            for (int mt = 0; mt < 4; mt++)
#pragma unroll
                for (int nt = 0; nt < 4; nt++)
                    mma_tf32(acc[mt][nt], afr[mt], bfr[nt]);
        }
        __syncthreads();
    }

    // Epilogue: + bias, BN1 (eval), ReLU, round to tf32 -> g_h1
#pragma unroll
    for (int nt = 0; nt < 4; nt++) {
        int c0 = block_n + wn * 32 + nt * 8 + tg * 2;
        float s0 = __ldg(bg + c0) * rsqrtf(__ldg(bv + c0) + BN_EPS);
        float s1 = __ldg(bg + c0 + 1) * rsqrtf(__ldg(bv + c0 + 1) + BN_EPS);
        float mu0 = __ldg(bm + c0), mu1 = __ldg(bm + c0 + 1);
        float be0 = __ldg(bb + c0), be1 = __ldg(bb + c0 + 1);
        float bi0 = __ldg(b1 + c0), bi1 = __ldg(b1 + c0 + 1);
#pragma unroll
        for (int mt = 0; mt < 4; mt++) {
            int r0 = block_m + wm * 64 + mt * 16 + gq;
#pragma unroll
            for (int h = 0; h < 2; h++) {
                int r = r0 + h * 8;
                if (r < N_NODES) {
                    float v0 = acc[mt][nt][h * 2 + 0] + bi0;
                    float v1 = acc[mt][nt][h * 2 + 1] + bi1;
                    v0 = fmaxf((v0 - mu0) * s0 + be0, 0.f);
                    v1 = fmaxf((v1 - mu1) * s1 + be1, 0.f);
                    g_h1[(size_t)r * HID + c0] = __uint_as_float(tf32r(v0));
                    g_h1[(size_t)r * HID + c0 + 1] = __uint_as_float(tf32r(v1));
                }
            }
        }
    }
}

// ---------------------------------------------------------------------------
// K4: GEMM2 [50000,256]x[256,40] TF32 mma, cp.async 2-stage pipeline.
//     CTA 128x40, 8 warps, warp m16 x 5 n8, K chunk 32.
//     A (g_h1) and B (g_w2tf) are pre-rounded -> raw async copies.
// ---------------------------------------------------------------------------
__global__ void __launch_bounds__(256)
gemm2_kernel(const float* __restrict__ b2, float* __restrict__ out) {
    __shared__ __align__(16) unsigned sA[2][128][36];  // [buf][m][k]
    __shared__ __align__(16) unsigned sB[2][32][44];   // [buf][k][n], 44%32=12 CF
    int tid = threadIdx.x;
    int warp = tid >> 5, lane = tid & 31;
    int gq = lane >> 2, tg = lane & 3;
    int block_m = blockIdx.x * 128;

    // Fixed per-thread load coordinates
    int a_row[4], a_c4[4], a_sz[4];
    const float* a_gp0[4];
#pragma unroll
    for (int i = 0; i < 4; i++) {
        int f4 = tid + i * 256;          // 0..1023
        a_row[i] = f4 >> 3;              // 0..127
        a_c4[i] = f4 & 7;                // 0..7
        int gr = block_m + a_row[i];
        a_sz[i] = (gr < N_NODES) ? 16 : 0;
        a_gp0[i] = g_h1 + (size_t)min(gr, N_NODES - 1) * HID + a_c4[i] * 4;
    }
    // B: 32 rows x 40 cols = 320 float4; thread tid handles f4=tid (<320) and tid+256 (<320)
    int b_k[2], b_c4[2], b_on[2];
#pragma unroll
    for (int i = 0; i < 2; i++) {
        int f4 = tid + i * 256;
        b_on[i] = (f4 < 320);
        int ff = b_on[i] ? f4 : 0;
        b_k[i] = ff / 10;
        b_c4[i] = ff - b_k[i] * 10;
    }

#define G2_ISSUE(chunk, buf)                                                     \
    {                                                                            \
        int kk_ = (chunk) * 32;                                                  \
        _Pragma("unroll")                                                        \
        for (int i = 0; i < 4; i++)                                              \
            cp_async16(smem_u32(&sA[(buf)][a_row[i]][a_c4[i] * 4]),              \
                       a_gp0[i] + kk_, a_sz[i]);                                 \
        _Pragma("unroll")                                                        \
        for (int i = 0; i < 2; i++)                                              \
            if (b_on[i])                                                         \
                cp_async16(smem_u32(&sB[(buf)][b_k[i]][b_c4[i] * 4]),            \
                           g_w2tf + (size_t)(kk_ + b_k[i]) * NCLS + b_c4[i] * 4, \
                           16);                                                  \
        cp_commit();                                                             \
    }

    float acc[5][4];
#pragma unroll
    for (int nt = 0; nt < 5; nt++)
#pragma unroll
        for (int r = 0; r < 4; r++) acc[nt][r] = 0.f;

    G2_ISSUE(0, 0);

    const int NITER = HID / 32;          // 8
#pragma unroll
    for (int it = 0; it < NITER; it++) {
        if (it < NITER - 1) {
            G2_ISSUE(it + 1, (it + 1) & 1);
            cp_wait<1>();
        } else {
            cp_wait<0>();
        }
        __syncthreads();
        int p = it & 1;
#pragma unroll
        for (int k8 = 0; k8 < 4; k8++) {
            int kb = k8 * 8;
            unsigned afr[4];
            int r = warp * 16;
            afr[0] = sA[p][r + gq][kb + tg];
            afr[1] = sA[p][r + gq + 8][kb + tg];
            afr[2] = sA[p][r + gq][kb + tg + 4];
            afr[3] = sA[p][r + gq + 8][kb + tg + 4];
#pragma unroll
            for (int nt = 0; nt < 5; nt++) {
                unsigned bfr[2];
                int c = nt * 8 + gq;
                bfr[0] = sB[p][kb + tg][c];
                bfr[1] = sB[p][kb + tg + 4][c];
                mma_tf32(acc[nt], afr, bfr);
            }
        }
        __syncthreads();
    }
#undef G2_ISSUE

    // Epilogue: z -> g_z; z + b2 -> out
#pragma unroll
    for (int nt = 0; nt < 5; nt++) {
        int c0 = nt * 8 + tg * 2;
        float bi0 = __ldg(b2 + c0), bi1 = __ldg(b2 + c0 + 1);
        int r0 = block_m + warp * 16 + gq;
#pragma unroll
        for (int h = 0; h < 2; h++) {
            int r = r0 + h * 8;
            if (r < N_NODES) {
                float v0 = acc[nt][h * 2 + 0];
                float v1 = acc[nt][h * 2 + 1];
                g_z[(size_t)r * NCLS + c0] = v0;
                g_z[(size_t)r * NCLS + c0 + 1] = v1;
                out[(size_t)r * NCLS + c0] = v0 + bi0;
                out[(size_t)r * NCLS + c0 + 1] = v1 + bi1;
            }
        }
    }
}

// ---------------------------------------------------------------------------
// K5: edge scatter-add in logit space (40 floats/edge = 10 float4 chunks).
// ---------------------------------------------------------------------------
__global__ void scatter40_kernel(const int* __restrict__ src,
                                 const int* __restrict__ dst,
                                 float* __restrict__ out) {
    int t = blockIdx.x * blockDim.x + threadIdx.x;
    int e = t / (NCLS / 4);
    if (e >= N_EDGES) return;
    int chunk = t - e * (NCLS / 4);
    int s = clamp_idx(__ldg(src + e));
    int d = clamp_idx(__ldg(dst + e));
    float4 v = *(const float4*)(g_z + (size_t)s * NCLS + chunk * 4);
    float* p = out + (size_t)d * NCLS + chunk * 4;
    red_add_v4(p, v);
}

// ---------------------------------------------------------------------------
extern "C" void kernel_launch(void* const* d_in, const int* in_sizes, int n_in,
                              void* d_out, int out_size) {
    const float* x = (const float*)d_in[0];
    const int* ei = (const int*)d_in[1];   // int32 (jax x64-disabled)
    const float* bn0g = (const float*)d_in[2];
    const float* bn0b = (const float*)d_in[3];
    const float* bn0m = (const float*)d_in[4];
    const float* bn0v = (const float*)d_in[5];
    const float* W1 = (const float*)d_in[6];
    const float* b1 = (const float*)d_in[7];
    const float* bn1g = (const float*)d_in[8];
    const float* bn1b = (const float*)d_in[9];
    const float* bn1m = (const float*)d_in[10];
    const float* bn1v = (const float*)d_in[11];
    const float* W2 = (const float*)d_in[12];
    const float* b2 = (const float*)d_in[13];
    float* out = (float*)d_out;

    const int* src = ei;
    const int* dst = ei + N_EDGES;

    // K0: pre-round weights to tf32
    convert_w_kernel<<<(F_IN * HID + 255) / 256, 256>>>(W1, W2);
    // K1: BN0 -> g_h0, g_agg1
    {
        int total = N_NODES * (F_IN / 4);
        bn0_kernel<<<(total + 255) / 256, 256>>>((const float4*)x, bn0g, bn0b, bn0m, bn0v);
    }
    // K2: 128-dim scatter-add into g_agg1 (v4 reductions)
    {
        long long threads = (long long)N_EDGES * 32;
        scatter128_kernel<<<(int)((threads + 255) / 256), 256>>>(src, dst);
    }
    // K3: GEMM1 (tf32 mma, BN=128) + BN1 + ReLU -> g_h1 (tf32-rounded)
    {
        dim3 grid((N_NODES + 127) / 128, HID / 128);
        gemm1_kernel<<<grid, 256>>>(b1, bn1g, bn1b, bn1m, bn1v);
    }
    // K4: GEMM2 (tf32 mma, cp.async pipeline) -> g_z, out = z + b2
    {
        gemm2_kernel<<<(N_NODES + 127) / 128, 256>>>(b2, out);
    }
    // K5: 40-dim scatter-add into out
    {
        long long threads = (long long)N_EDGES * (NCLS / 4);
        scatter40_kernel<<<(int)((threads + 255) / 256), 256>>>(src, dst, out);
    }
}

// round 12
// speedup vs baseline: 2.0443x; 1.3234x over previous
#include <cuda_runtime.h>
#include <math.h>
#include <stdint.h>

#define N_NODES 50000
#define F_IN 128
#define HID 256
#define NCLS 40
#define N_EDGES 600000
#define BN_EPS 1e-5f
#define SCAN_BLK 1024
#define N_SCAN_BLOCKS ((N_NODES + SCAN_BLK - 1) / SCAN_BLK)   // 49

// Scratch (static device globals -- no runtime allocation allowed)
__device__ float g_h0[N_NODES * F_IN];    // BN0(x)
__device__ float g_agg1[N_NODES * F_IN];  // gather result, tf32-rounded
__device__ float g_h1[N_NODES * HID];     // relu(BN1(...)), tf32-rounded
__device__ float g_z[N_NODES * NCLS];     // h1 @ W2 (pre-aggregation logits)
__device__ float g_w1tf[F_IN * HID];      // W1 pre-rounded to tf32
__device__ float g_w2tf[HID * NCLS];      // W2 pre-rounded to tf32
// CSR-by-dst scratch
__device__ int g_deg[N_NODES];
__device__ int g_roff[N_NODES];           // exclusive offsets
__device__ int g_cur[N_NODES];            // fill cursors
__device__ int g_part[64];                // per-block scan partials
__device__ int g_eidx[N_EDGES];           // src ids grouped by dst

__device__ __forceinline__ int clamp_idx(int i) {
    i = i < 0 ? 0 : i;
    return i >= N_NODES ? N_NODES - 1 : i;
}

// Round-to-nearest f32 -> tf32 (kept in 32-bit container)
__device__ __forceinline__ unsigned tf32r(float x) {
    unsigned r;
    asm("cvt.rna.tf32.f32 %0, %1;" : "=r"(r) : "f"(x));
    return r;
}

// D += A*B for one m16n8k8 tf32 tile
__device__ __forceinline__ void mma_tf32(float* d, const unsigned* a, const unsigned* b) {
    asm volatile(
        "mma.sync.aligned.m16n8k8.row.col.f32.tf32.tf32.f32 "
        "{%0,%1,%2,%3}, {%4,%5,%6,%7}, {%8,%9}, {%0,%1,%2,%3};"
        : "+f"(d[0]), "+f"(d[1]), "+f"(d[2]), "+f"(d[3])
        : "r"(a[0]), "r"(a[1]), "r"(a[2]), "r"(a[3]), "r"(b[0]), "r"(b[1]));
}

__device__ __forceinline__ void cp_async16(uint32_t saddr, const void* gptr, int sz) {
    asm volatile("cp.async.cg.shared.global [%0], [%1], 16, %2;"
                 :: "r"(saddr), "l"(gptr), "r"(sz) : "memory");
}
__device__ __forceinline__ void cp_commit() {
    asm volatile("cp.async.commit_group;" ::: "memory");
}
template <int N>
__device__ __forceinline__ void cp_wait() {
    asm volatile("cp.async.wait_group %0;" :: "n"(N) : "memory");
}
__device__ __forceinline__ uint32_t smem_u32(const void* p) {
    return (uint32_t)__cvta_generic_to_shared(p);
}

// ---------------------------------------------------------------------------
// K0: one-time weight pre-rounding to tf32
// ---------------------------------------------------------------------------
__global__ void convert_w_kernel(const float* __restrict__ W1,
                                 const float* __restrict__ W2) {
    int i = blockIdx.x * blockDim.x + threadIdx.x;
    if (i < F_IN * HID) g_w1tf[i] = __uint_as_float(tf32r(W1[i]));
    if (i < HID * NCLS) g_w2tf[i] = __uint_as_float(tf32r(W2[i]));
}

// ---------------------------------------------------------------------------
// K1: BN0 over input features -> g_h0
// ---------------------------------------------------------------------------
__global__ void bn0_kernel(const float4* __restrict__ x,
                           const float* __restrict__ g, const float* __restrict__ b,
                           const float* __restrict__ m, const float* __restrict__ v) {
    int idx = blockIdx.x * blockDim.x + threadIdx.x;
    const int total = N_NODES * (F_IN / 4);
    if (idx >= total) return;
    int c = (idx & (F_IN / 4 - 1)) * 4;
    float4 xv = x[idx];
    float4 o;
    o.x = (xv.x - __ldg(m + c + 0)) * (__ldg(g + c + 0) * rsqrtf(__ldg(v + c + 0) + BN_EPS)) + __ldg(b + c + 0);
    o.y = (xv.y - __ldg(m + c + 1)) * (__ldg(g + c + 1) * rsqrtf(__ldg(v + c + 1) + BN_EPS)) + __ldg(b + c + 1);
    o.z = (xv.z - __ldg(m + c + 2)) * (__ldg(g + c + 2) * rsqrtf(__ldg(v + c + 2) + BN_EPS)) + __ldg(b + c + 2);
    o.w = (xv.w - __ldg(m + c + 3)) * (__ldg(g + c + 3) * rsqrtf(__ldg(v + c + 3) + BN_EPS)) + __ldg(b + c + 3);
    ((float4*)g_h0)[idx] = o;
}

// ---------------------------------------------------------------------------
// CSR build: zero -> hist -> block scan -> partial scan -> add -> fill
// ---------------------------------------------------------------------------
__global__ void zero_deg_kernel() {
    int i = blockIdx.x * blockDim.x + threadIdx.x;
    if (i < N_NODES) g_deg[i] = 0;
}

__global__ void hist_kernel(const int* __restrict__ dst) {
    int e = blockIdx.x * blockDim.x + threadIdx.x;
    if (e >= N_EDGES) return;
    atomicAdd(&g_deg[clamp_idx(__ldg(dst + e))], 1);
}

__global__ void scan_block_kernel() {
    __shared__ int wsum[32];
    int tid = threadIdx.x;
    int i = blockIdx.x * SCAN_BLK + tid;
    int lane = tid & 31, wid = tid >> 5;
    int v = (i < N_NODES) ? g_deg[i] : 0;
    int s = v;
#pragma unroll
    for (int off = 1; off < 32; off <<= 1) {
        int u = __shfl_up_sync(0xFFFFFFFFu, s, off);
        if (lane >= off) s += u;
    }
    if (lane == 31) wsum[wid] = s;
    __syncthreads();
    if (wid == 0) {
        int ws = wsum[lane];
        int t = ws;
#pragma unroll
        for (int off = 1; off < 32; off <<= 1) {
            int u = __shfl_up_sync(0xFFFFFFFFu, t, off);
            if (lane >= off) t += u;
        }
        wsum[lane] = t - ws;                  // exclusive warp prefix
        if (lane == 31) g_part[blockIdx.x] = t;  // block total
    }
    __syncthreads();
    if (i < N_NODES) g_roff[i] = s - v + wsum[wid];
}

__global__ void scan_part_kernel() {
    __shared__ int buf[64];
    int tid = threadIdx.x;
    int v = (tid < N_SCAN_BLOCKS) ? g_part[tid] : 0;
    buf[tid] = v;
    __syncthreads();
#pragma unroll
    for (int off = 1; off < 64; off <<= 1) {
        int t = (tid >= off) ? buf[tid - off] : 0;
        __syncthreads();
        buf[tid] += t;
        __syncthreads();
    }
    if (tid < N_SCAN_BLOCKS) g_part[tid] = buf[tid] - v;  // exclusive
}

__global__ void scan_add_kernel() {
    int i = blockIdx.x * blockDim.x + threadIdx.x;
    if (i >= N_NODES) return;
    int r = g_roff[i] + g_part[i / SCAN_BLK];
    g_roff[i] = r;
    g_cur[i] = r;
}

__global__ void fill_kernel(const int* __restrict__ src, const int* __restrict__ dst) {
    int e = blockIdx.x * blockDim.x + threadIdx.x;
    if (e >= N_EDGES) return;
    int d = clamp_idx(__ldg(dst + e));
    int s = clamp_idx(__ldg(src + e));
    int p = atomicAdd(&g_cur[d], 1);
    g_eidx[p] = s;
}

// ---------------------------------------------------------------------------
// K2: gather aggregation, F=128. One warp per node; lane owns one float4.
//     agg1[i] = h0[i] + sum_{j in N(i)} h0[j], written tf32-rounded.
// ---------------------------------------------------------------------------
__global__ void agg128_kernel() {
    int node = (blockIdx.x * blockDim.x + threadIdx.x) >> 5;
    if (node >= N_NODES) return;
    int lane = threadIdx.x & 31;
    float4 acc = ((const float4*)(g_h0 + (size_t)node * F_IN))[lane];
    int beg = g_roff[node];
    int end = (node + 1 < N_NODES) ? g_roff[node + 1] : N_EDGES;
    for (int j = beg; j < end; j++) {
        int s = __ldg(g_eidx + j);
        float4 v = ((const float4*)(g_h0 + (size_t)s * F_IN))[lane];
        acc.x += v.x; acc.y += v.y; acc.z += v.z; acc.w += v.w;
    }
    float4 o;
    o.x = __uint_as_float(tf32r(acc.x));
    o.y = __uint_as_float(tf32r(acc.y));
    o.z = __uint_as_float(tf32r(acc.z));
    o.w = __uint_as_float(tf32r(acc.w));
    ((float4*)(g_agg1 + (size_t)node * F_IN))[lane] = o;
}

// ---------------------------------------------------------------------------
// K3: GEMM1 [50000,128]x[128,256] + bias + BN1 + ReLU -> g_h1 (tf32-rounded).
//     TF32 mma, cp.async 2-stage pipeline. CTA 128x128, BK=16,
//     8 warps (2m x 4n), warp tile 64x32. A (g_agg1) and B (g_w1tf) pre-rounded.
// ---------------------------------------------------------------------------
__global__ void __launch_bounds__(256)
gemm1_kernel(const float* __restrict__ b1,
             const float* __restrict__ bg, const float* __restrict__ bb,
             const float* __restrict__ bm, const float* __restrict__ bv) {
    __shared__ __align__(16) unsigned sA[2][128][20];   // [buf][m][k], 20%32 CF
    __shared__ __align__(16) unsigned sB[2][16][136];   // [buf][k][n], 136%32=8 CF
    int tid = threadIdx.x;
    int warp = tid >> 5, lane = tid & 31;
    int wm = warp >> 2, wn = warp & 3;
    int gq = lane >> 2, tg = lane & 3;
    int block_m = blockIdx.x * 128;
    int block_n = blockIdx.y * 128;

    // A: 128 rows x 16 k = 512 float4; 2/thread
    int a_row[2], a_c4[2], a_sz[2];
    const float* a_gp0[2];
#pragma unroll
    for (int i = 0; i < 2; i++) {
        int f4 = tid + i * 256;          // 0..511
        a_row[i] = f4 >> 2;              // 0..127
        a_c4[i] = f4 & 3;                // 0..3
        int gr = block_m + a_row[i];
        a_sz[i] = (gr < N_NODES) ? 16 : 0;
        a_gp0[i] = g_agg1 + (size_t)min(gr, N_NODES - 1) * F_IN + a_c4[i] * 4;
    }
    // B: 16 rows x 32 f4 = 512 float4; 2/thread
    int b_k[2], b_c4[2];
#pragma unroll
    for (int i = 0; i < 2; i++) {
        int f4 = tid + i * 256;
        b_k[i] = f4 >> 5;                // 0..15
        b_c4[i] = f4 & 31;               // 0..31
    }

#define G1_ISSUE(chunk, buf)                                                      \
    {                                                                             \
        int kk_ = (chunk) * 16;                                                   \
        _Pragma("unroll")                                                         \
        for (int i = 0; i < 2; i++)                                               \
            cp_async16(smem_u32(&sA[(buf)][a_row[i]][a_c4[i] * 4]),               \
                       a_gp0[i] + kk_, a_sz[i]);                                  \
        _Pragma("unroll")                                                         \
        for (int i = 0; i < 2; i++)                                               \
            cp_async16(smem_u32(&sB[(buf)][b_k[i]][b_c4[i] * 4]),                 \
                       g_w1tf + (size_t)(kk_ + b_k[i]) * HID + block_n +          \
                           b_c4[i] * 4,                                           \
                       16);                                                       \
        cp_commit();                                                              \
    }

    float acc[4][4][4];
#pragma unroll
    for (int mt = 0; mt < 4; mt++)
#pragma unroll
        for (int nt = 0; nt < 4; nt++)
#pragma unroll
            for (int r = 0; r < 4; r++) acc[mt][nt][r] = 0.f;

    G1_ISSUE(0, 0);

    const int NITER = F_IN / 16;         // 8
#pragma unroll
    for (int it = 0; it < NITER; it++) {
        if (it < NITER - 1) {
            G1_ISSUE(it + 1, (it + 1) & 1);
            cp_wait<1>();
        } else {
            cp_wait<0>();
        }
        __syncthreads();
        int p = it & 1;
#pragma unroll
        for (int k8 = 0; k8 < 2; k8++) {
            int kb = k8 * 8;
            unsigned afr[4][4];
#pragma unroll
            for (int mt = 0; mt < 4; mt++) {
                int r = wm * 64 + mt * 16;
                afr[mt][0] = sA[p][r + gq][kb + tg];
                afr[mt][1] = sA[p][r + gq + 8][kb + tg];
                afr[mt][2] = sA[p][r + gq][kb + tg + 4];
                afr[mt][3] = sA[p][r + gq + 8][kb + tg + 4];
            }
            unsigned bfr[4][2];
#pragma unroll
            for (int nt = 0; nt < 4; nt++) {
                int c = wn * 32 + nt * 8 + gq;
                bfr[nt][0] = sB[p][kb + tg][c];
                bfr[nt][1] = sB[p][kb + tg + 4][c];
            }
#pragma unroll
            for (int mt = 0; mt < 4; mt++)
#pragma unroll
                for (int nt = 0; nt < 4; nt++)
                    mma_tf32(acc[mt][nt], afr[mt], bfr[nt]);
        }
        __syncthreads();
    }
#undef G1_ISSUE

    // Epilogue: + bias, BN1 (eval), ReLU, round to tf32 -> g_h1
#pragma unroll
    for (int nt = 0; nt < 4; nt++) {
        int c0 = block_n + wn * 32 + nt * 8 + tg * 2;
        float s0 = __ldg(bg + c0) * rsqrtf(__ldg(bv + c0) + BN_EPS);
        float s1 = __ldg(bg + c0 + 1) * rsqrtf(__ldg(bv + c0 + 1) + BN_EPS);
        float mu0 = __ldg(bm + c0), mu1 = __ldg(bm + c0 + 1);
        float be0 = __ldg(bb + c0), be1 = __ldg(bb + c0 + 1);
        float bi0 = __ldg(b1 + c0), bi1 = __ldg(b1 + c0 + 1);
#pragma unroll
        for (int mt = 0; mt < 4; mt++) {
            int r0 = block_m + wm * 64 + mt * 16 + gq;
#pragma unroll
            for (int h = 0; h < 2; h++) {
                int r = r0 + h * 8;
                if (r < N_NODES) {
                    float v0 = acc[mt][nt][h * 2 + 0] + bi0;
                    float v1 = acc[mt][nt][h * 2 + 1] + bi1;
                    v0 = fmaxf((v0 - mu0) * s0 + be0, 0.f);
                    v1 = fmaxf((v1 - mu1) * s1 + be1, 0.f);
                    g_h1[(size_t)r * HID + c0] = __uint_as_float(tf32r(v0));
                    g_h1[(size_t)r * HID + c0 + 1] = __uint_as_float(tf32r(v1));
                }
            }
        }
    }
}

// ---------------------------------------------------------------------------
// K4: GEMM2 [50000,256]x[256,40] TF32 mma, cp.async 2-stage pipeline.
//     CTA 128x40, 8 warps, warp m16 x 5 n8, K chunk 32. Writes g_z only.
// ---------------------------------------------------------------------------
__global__ void __launch_bounds__(256)
gemm2_kernel() {
    __shared__ __align__(16) unsigned sA[2][128][36];
    __shared__ __align__(16) unsigned sB[2][32][44];
    int tid = threadIdx.x;
    int warp = tid >> 5, lane = tid & 31;
    int gq = lane >> 2, tg = lane & 3;
    int block_m = blockIdx.x * 128;

    int a_row[4], a_c4[4], a_sz[4];
    const float* a_gp0[4];
#pragma unroll
    for (int i = 0; i < 4; i++) {
        int f4 = tid + i * 256;
        a_row[i] = f4 >> 3;
        a_c4[i] = f4 & 7;
        int gr = block_m + a_row[i];
        a_sz[i] = (gr < N_NODES) ? 16 : 0;
        a_gp0[i] = g_h1 + (size_t)min(gr, N_NODES - 1) * HID + a_c4[i] * 4;
    }
    int b_k[2], b_c4[2], b_on[2];
#pragma unroll
    for (int i = 0; i < 2; i++) {
        int f4 = tid + i * 256;
        b_on[i] = (f4 < 320);
        int ff = b_on[i] ? f4 : 0;
        b_k[i] = ff / 10;
        b_c4[i] = ff - b_k[i] * 10;
    }

#define G2_ISSUE(chunk, buf)                                                     \
    {                                                                            \
        int kk_ = (chunk) * 32;                                                  \
        _Pragma("unroll")                                                        \
        for (int i = 0; i < 4; i++)                                              \
            cp_async16(smem_u32(&sA[(buf)][a_row[i]][a_c4[i] * 4]),              \
                       a_gp0[i] + kk_, a_sz[i]);                                 \
        _Pragma("unroll")                                                        \
        for (int i = 0; i < 2; i++)                                              \
            if (b_on[i])                                                         \
                cp_async16(smem_u32(&sB[(buf)][b_k[i]][b_c4[i] * 4]),            \
                           g_w2tf + (size_t)(kk_ + b_k[i]) * NCLS + b_c4[i] * 4, \
                           16);                                                  \
        cp_commit();                                                             \
    }

    float acc[5][4];
#pragma unroll
    for (int nt = 0; nt < 5; nt++)
#pragma unroll
        for (int r = 0; r < 4; r++) acc[nt][r] = 0.f;

    G2_ISSUE(0, 0);

    const int NITER = HID / 32;
#pragma unroll
    for (int it = 0; it < NITER; it++) {
        if (it < NITER - 1) {
            G2_ISSUE(it + 1, (it + 1) & 1);
            cp_wait<1>();
        } else {
            cp_wait<0>();
        }
        __syncthreads();
        int p = it & 1;
#pragma unroll
        for (int k8 = 0; k8 < 4; k8++) {
            int kb = k8 * 8;
            unsigned afr[4];
            int r = warp * 16;
            afr[0] = sA[p][r + gq][kb + tg];
            afr[1] = sA[p][r + gq + 8][kb + tg];
            afr[2] = sA[p][r + gq][kb + tg + 4];
            afr[3] = sA[p][r + gq + 8][kb + tg + 4];
#pragma unroll
            for (int nt = 0; nt < 5; nt++) {
                unsigned bfr[2];
                int c = nt * 8 + gq;
                bfr[0] = sB[p][kb + tg][c];
                bfr[1] = sB[p][kb + tg + 4][c];
                mma_tf32(acc[nt], afr, bfr);
            }
        }
        __syncthreads();
    }
#undef G2_ISSUE

#pragma unroll
    for (int nt = 0; nt < 5; nt++) {
        int c0 = nt * 8 + tg * 2;
        int r0 = block_m + warp * 16 + gq;
#pragma unroll
        for (int h = 0; h < 2; h++) {
            int r = r0 + h * 8;
            if (r < N_NODES) {
                g_z[(size_t)r * NCLS + c0] = acc[nt][h * 2 + 0];
                g_z[(size_t)r * NCLS + c0 + 1] = acc[nt][h * 2 + 1];
            }
        }
    }
}

// ---------------------------------------------------------------------------
// K5: gather in logit space + self term + bias.
//     out[i] = z[i] + sum_{j in N(i)} z[j] + b2. Thread = (node, chunk of 4).
// ---------------------------------------------------------------------------
__global__ void gather40_kernel(const float* __restrict__ b2,
                                float* __restrict__ out) {
    int t = blockIdx.x * blockDim.x + threadIdx.x;
    int node = t / (NCLS / 4);
    if (node >= N_NODES) return;
    int chunk = t - node * (NCLS / 4);
    float4 acc = *(const float4*)(g_z + (size_t)node * NCLS + chunk * 4);
    int beg = g_roff[node];
    int end = (node + 1 < N_NODES) ? g_roff[node + 1] : N_EDGES;
    for (int j = beg; j < end; j++) {
        int s = __ldg(g_eidx + j);
        float4 v = *(const float4*)(g_z + (size_t)s * NCLS + chunk * 4);
        acc.x += v.x; acc.y += v.y; acc.z += v.z; acc.w += v.w;
    }
    acc.x += __ldg(b2 + chunk * 4 + 0);
    acc.y += __ldg(b2 + chunk * 4 + 1);
    acc.z += __ldg(b2 + chunk * 4 + 2);
    acc.w += __ldg(b2 + chunk * 4 + 3);
    *(float4*)(out + (size_t)node * NCLS + chunk * 4) = acc;
}

// ---------------------------------------------------------------------------
extern "C" void kernel_launch(void* const* d_in, const int* in_sizes, int n_in,
                              void* d_out, int out_size) {
    const float* x = (const float*)d_in[0];
    const int* ei = (const int*)d_in[1];   // int32 (jax x64-disabled)
    const float* bn0g = (const float*)d_in[2];
    const float* bn0b = (const float*)d_in[3];
    const float* bn0m = (const float*)d_in[4];
    const float* bn0v = (const float*)d_in[5];
    const float* W1 = (const float*)d_in[6];
    const float* b1 = (const float*)d_in[7];
    const float* bn1g = (const float*)d_in[8];
    const float* bn1b = (const float*)d_in[9];
    const float* bn1m = (const float*)d_in[10];
    const float* bn1v = (const float*)d_in[11];
    const float* W2 = (const float*)d_in[12];
    const float* b2 = (const float*)d_in[13];
    float* out = (float*)d_out;

    const int* src = ei;
    const int* dst = ei + N_EDGES;

    // K0: pre-round weights to tf32
    convert_w_kernel<<<(F_IN * HID + 255) / 256, 256>>>(W1, W2);
    // K1: BN0 -> g_h0
    {
        int total = N_NODES * (F_IN / 4);
        bn0_kernel<<<(total + 255) / 256, 256>>>((const float4*)x, bn0g, bn0b, bn0m, bn0v);
    }
    // CSR build (by dst)
    zero_deg_kernel<<<(N_NODES + 255) / 256, 256>>>();
    hist_kernel<<<(N_EDGES + 255) / 256, 256>>>(dst);
    scan_block_kernel<<<N_SCAN_BLOCKS, SCAN_BLK>>>();
    scan_part_kernel<<<1, 64>>>();
    scan_add_kernel<<<(N_NODES + 255) / 256, 256>>>();
    fill_kernel<<<(N_EDGES + 255) / 256, 256>>>(src, dst);
    // K2: gather aggregation (F=128) -> g_agg1 (tf32-rounded)
    {
        long long threads = (long long)N_NODES * 32;
        agg128_kernel<<<(int)((threads + 255) / 256), 256>>>();
    }
    // K3: GEMM1 (tf32 mma, cp.async) + BN1 + ReLU -> g_h1
    {
        dim3 grid((N_NODES + 127) / 128, HID / 128);
        gemm1_kernel<<<grid, 256>>>(b1, bn1g, bn1b, bn1m, bn1v);
    }
    // K4: GEMM2 (tf32 mma, cp.async) -> g_z
    gemm2_kernel<<<(N_NODES + 127) / 128, 256>>>();
    // K5: gather in logit space + self + bias -> out
    {
        long long threads = (long long)N_NODES * (NCLS / 4);
        gather40_kernel<<<(int)((threads + 255) / 256), 256>>>(b2, out);
    }
}